// round 1
// baseline (speedup 1.0000x reference)
#include <cuda_runtime.h>
#include <cuda_bf16.h>

#define B_   2
#define S_   2048
#define HID_ 768
#define NH_  12
#define HD_  64
#define T_   (B_*S_)   // 4096

// ---------------- scratch (static device arrays; no allocation) ----------------
__device__ __nv_bfloat16 g_Xhi[T_*HID_];
__device__ __nv_bfloat16 g_Xlo[T_*HID_];
__device__ __nv_bfloat16 g_Whi[3][HID_*HID_];
__device__ __nv_bfloat16 g_Wlo[3][HID_*HID_];
__device__ __nv_bfloat16 g_qhi[B_*NH_*S_*HD_];
__device__ __nv_bfloat16 g_qlo[B_*NH_*S_*HD_];
__device__ __nv_bfloat16 g_khi[B_*NH_*S_*HD_];
__device__ __nv_bfloat16 g_klo[B_*NH_*S_*HD_];
__device__ __nv_bfloat16 g_vhi[B_*NH_*S_*HD_];
__device__ __nv_bfloat16 g_vlo[B_*NH_*S_*HD_];

// ---------------- helpers ----------------
__device__ __forceinline__ void mma16816(float c[4], const unsigned a[4],
                                         unsigned b0, unsigned b1) {
    asm volatile(
        "mma.sync.aligned.m16n8k16.row.col.f32.bf16.bf16.f32 "
        "{%0,%1,%2,%3},{%4,%5,%6,%7},{%8,%9},{%0,%1,%2,%3};\n"
        : "+f"(c[0]), "+f"(c[1]), "+f"(c[2]), "+f"(c[3])
        : "r"(a[0]), "r"(a[1]), "r"(a[2]), "r"(a[3]), "r"(b0), "r"(b1));
}

__device__ __forceinline__ float ex2(float x) {
    float y;
    asm("ex2.approx.f32 %0, %1;" : "=f"(y) : "f"(x));
    return y;
}

// pack two floats into (hi bf16x2, lo bf16x2) — lo = residual
__device__ __forceinline__ void split2(float a, float b, unsigned &hi, unsigned &lo) {
    __nv_bfloat16 ha = __float2bfloat16(a);
    __nv_bfloat16 hb = __float2bfloat16(b);
    __nv_bfloat16 la = __float2bfloat16(a - __bfloat162float(ha));
    __nv_bfloat16 lb = __float2bfloat16(b - __bfloat162float(hb));
    __nv_bfloat162 th; th.x = ha; th.y = hb;
    __nv_bfloat162 tl; tl.x = la; tl.y = lb;
    hi = *reinterpret_cast<unsigned*>(&th);
    lo = *reinterpret_cast<unsigned*>(&tl);
}

// ---------------- split fp32 -> bf16 hi/lo ----------------
__global__ void split_kernel(const float* __restrict__ src,
                             __nv_bfloat16* __restrict__ hi,
                             __nv_bfloat16* __restrict__ lo, int n) {
    int i = blockIdx.x * 256 + threadIdx.x;
    if (i < n) {
        float v = src[i];
        __nv_bfloat16 h = __float2bfloat16(v);
        hi[i] = h;
        lo[i] = __float2bfloat16(v - __bfloat162float(h));
    }
}

// ---------------- QKV projection GEMM ----------------
// out[t][o] = sum_i X[t][i] * W[o][i] (+bias) * scale, split-bf16 3-term mma.
// CTA: 128(M) x 128(N), K step 32. 8 warps as 4(M) x 2(N), warp tile 32x64.
__global__ __launch_bounds__(256) void qkv_gemm(
    const float* __restrict__ bq, const float* __restrict__ bk,
    const float* __restrict__ bv) {
    const int proj = blockIdx.z;
    const __nv_bfloat16* __restrict__ Bh = g_Whi[proj];
    const __nv_bfloat16* __restrict__ Bl = g_Wlo[proj];
    const float* bias = (proj == 0) ? bq : (proj == 1) ? bk : bv;
    const float scale = (proj == 0) ? 0.125f : 1.0f;
    __nv_bfloat16* out_hi = (proj == 0) ? g_qhi : (proj == 1) ? g_khi : g_vhi;
    __nv_bfloat16* out_lo = (proj == 0) ? g_qlo : (proj == 1) ? g_klo : g_vlo;

    const int mbase = blockIdx.x * 128, nbase = blockIdx.y * 128;
    const int tid = threadIdx.x, warp = tid >> 5, lane = tid & 31;
    const int lr = lane >> 2, lc = lane & 3;
    const int wm = (warp & 3) * 32, wn = (warp >> 2) * 64;

    __shared__ __nv_bfloat16 sAhi[128 * 40], sAlo[128 * 40];
    __shared__ __nv_bfloat16 sBhi[128 * 40], sBlo[128 * 40];

    float acc[2][8][4];
#pragma unroll
    for (int i = 0; i < 2; ++i)
#pragma unroll
        for (int j = 0; j < 8; ++j)
#pragma unroll
            for (int k = 0; k < 4; ++k) acc[i][j][k] = 0.f;

    const int r = tid >> 1, hf = tid & 1;  // 128 rows, 2 halves of 16 bf16

    for (int k0 = 0; k0 < HID_; k0 += 32) {
        __syncthreads();
        {
            const long ga = (long)(mbase + r) * HID_ + k0 + hf * 16;
            const uint4* pah = reinterpret_cast<const uint4*>(g_Xhi + ga);
            const uint4* pal = reinterpret_cast<const uint4*>(g_Xlo + ga);
            uint4 a0 = pah[0], a1 = pah[1], a2 = pal[0], a3 = pal[1];
            *reinterpret_cast<uint4*>(&sAhi[r * 40 + hf * 16]) = a0;
            *reinterpret_cast<uint4*>(&sAhi[r * 40 + hf * 16 + 8]) = a1;
            *reinterpret_cast<uint4*>(&sAlo[r * 40 + hf * 16]) = a2;
            *reinterpret_cast<uint4*>(&sAlo[r * 40 + hf * 16 + 8]) = a3;
            const long gb = (long)(nbase + r) * HID_ + k0 + hf * 16;
            const uint4* pbh = reinterpret_cast<const uint4*>(Bh + gb);
            const uint4* pbl = reinterpret_cast<const uint4*>(Bl + gb);
            uint4 b0 = pbh[0], b1 = pbh[1], b2 = pbl[0], b3 = pbl[1];
            *reinterpret_cast<uint4*>(&sBhi[r * 40 + hf * 16]) = b0;
            *reinterpret_cast<uint4*>(&sBhi[r * 40 + hf * 16 + 8]) = b1;
            *reinterpret_cast<uint4*>(&sBlo[r * 40 + hf * 16]) = b2;
            *reinterpret_cast<uint4*>(&sBlo[r * 40 + hf * 16 + 8]) = b3;
        }
        __syncthreads();
#pragma unroll
        for (int ks = 0; ks < 2; ++ks) {
            const int kk = ks * 16;
            unsigned ah[2][4], al[2][4];
#pragma unroll
            for (int mt = 0; mt < 2; ++mt) {
                const int rr = wm + mt * 16 + lr;
                const int cc = kk + 2 * lc;
                ah[mt][0] = *reinterpret_cast<unsigned*>(&sAhi[rr * 40 + cc]);
                ah[mt][1] = *reinterpret_cast<unsigned*>(&sAhi[(rr + 8) * 40 + cc]);
                ah[mt][2] = *reinterpret_cast<unsigned*>(&sAhi[rr * 40 + cc + 8]);
                ah[mt][3] = *reinterpret_cast<unsigned*>(&sAhi[(rr + 8) * 40 + cc + 8]);
                al[mt][0] = *reinterpret_cast<unsigned*>(&sAlo[rr * 40 + cc]);
                al[mt][1] = *reinterpret_cast<unsigned*>(&sAlo[(rr + 8) * 40 + cc]);
                al[mt][2] = *reinterpret_cast<unsigned*>(&sAlo[rr * 40 + cc + 8]);
                al[mt][3] = *reinterpret_cast<unsigned*>(&sAlo[(rr + 8) * 40 + cc + 8]);
            }
#pragma unroll
            for (int nt = 0; nt < 8; ++nt) {
                const int nn = wn + nt * 8 + lr;
                const int cc = kk + 2 * lc;
                unsigned bh0 = *reinterpret_cast<unsigned*>(&sBhi[nn * 40 + cc]);
                unsigned bh1 = *reinterpret_cast<unsigned*>(&sBhi[nn * 40 + cc + 8]);
                unsigned bl0 = *reinterpret_cast<unsigned*>(&sBlo[nn * 40 + cc]);
                unsigned bl1 = *reinterpret_cast<unsigned*>(&sBlo[nn * 40 + cc + 8]);
#pragma unroll
                for (int mt = 0; mt < 2; ++mt) {
                    mma16816(acc[mt][nt], ah[mt], bh0, bh1);
                    mma16816(acc[mt][nt], ah[mt], bl0, bl1);
                    mma16816(acc[mt][nt], al[mt], bh0, bh1);
                }
            }
        }
    }

    // write split-bf16 outputs in [B,NH,S,HD] layout
#pragma unroll
    for (int mt = 0; mt < 2; ++mt) {
#pragma unroll
        for (int nt = 0; nt < 8; ++nt) {
            const int row0 = mbase + wm + mt * 16 + lr;
            const int col0 = nbase + wn + nt * 8 + 2 * lc;
#pragma unroll
            for (int rr = 0; rr < 2; ++rr) {
                const int t = row0 + rr * 8;
                float v0 = (acc[mt][nt][rr * 2 + 0] + bias[col0]) * scale;
                float v1 = (acc[mt][nt][rr * 2 + 1] + bias[col0 + 1]) * scale;
                const int bb = t >> 11, ss = t & 2047;
                const int h = col0 >> 6, d = col0 & 63;
                const long oidx = (((long)bb * NH_ + h) * S_ + ss) * HD_ + d;
                unsigned hi, lo;
                split2(v0, v1, hi, lo);
                *reinterpret_cast<unsigned*>(out_hi + oidx) = hi;
                *reinterpret_cast<unsigned*>(out_lo + oidx) = lo;
            }
        }
    }
}

// ---------------- flash attention ----------------
// CTA: 128 q rows (8 warps x 16), key blocks of 64, online softmax.
__global__ __launch_bounds__(256, 2) void attn_kernel(
    const float* __restrict__ rel_pos, const float* __restrict__ rel2d,
    const int* __restrict__ amask, float* __restrict__ out) {
    const int qt = blockIdx.x, h = blockIdx.y, b = blockIdx.z;
    const int bh = b * NH_ + h;
    const int tid = threadIdx.x, warp = tid >> 5, lane = tid & 31;
    const int qbase = qt * 128;
    const int lr = lane >> 2, lc = lane & 3;
    const float L2E = 1.4426950408889634f;

    __shared__ __nv_bfloat16 sKhi[64 * 72], sKlo[64 * 72];
    __shared__ __nv_bfloat16 sVhi[64 * 72], sVlo[64 * 72];  // transposed: [d][t]

    // q fragments (A-frags), loaded once directly from global
    unsigned qh[4][4], ql[4][4];
    {
        const __nv_bfloat16* qhp =
            g_qhi + ((long)bh * S_ + qbase + warp * 16) * HD_;
        const __nv_bfloat16* qlp =
            g_qlo + ((long)bh * S_ + qbase + warp * 16) * HD_;
#pragma unroll
        for (int ks = 0; ks < 4; ++ks) {
            const int b0 = lr * HD_ + ks * 16 + 2 * lc;
            qh[ks][0] = *reinterpret_cast<const unsigned*>(qhp + b0);
            qh[ks][1] = *reinterpret_cast<const unsigned*>(qhp + b0 + 8 * HD_);
            qh[ks][2] = *reinterpret_cast<const unsigned*>(qhp + b0 + 8);
            qh[ks][3] = *reinterpret_cast<const unsigned*>(qhp + b0 + 8 * HD_ + 8);
            ql[ks][0] = *reinterpret_cast<const unsigned*>(qlp + b0);
            ql[ks][1] = *reinterpret_cast<const unsigned*>(qlp + b0 + 8 * HD_);
            ql[ks][2] = *reinterpret_cast<const unsigned*>(qlp + b0 + 8);
            ql[ks][3] = *reinterpret_cast<const unsigned*>(qlp + b0 + 8 * HD_ + 8);
        }
    }

    float O[8][4];
#pragma unroll
    for (int i = 0; i < 8; ++i)
#pragma unroll
        for (int j = 0; j < 4; ++j) O[i][j] = 0.f;
    float m0 = -1e30f, m1 = -1e30f, l0 = 0.f, l1 = 0.f;

    const float* rp_row = rel_pos + ((long)bh * S_ + qbase + warp * 16 + lr) * S_;
    const float* r2_row = rel2d + ((long)bh * S_ + qbase + warp * 16 + lr) * S_;
    const int* mk_row = amask + ((long)b * S_ + qbase + warp * 16 + lr) * S_;

    const int trow = tid >> 2;         // 0..63
    const int dof = (tid & 3) * 16;    // 0,16,32,48

    for (int kb = 0; kb < 32; ++kb) {
        const int kbase = kb * 64;
        __syncthreads();
        {
            const long gofs = ((long)bh * S_ + kbase + trow) * HD_ + dof;
            const uint4* gkh = reinterpret_cast<const uint4*>(g_khi + gofs);
            const uint4* gkl = reinterpret_cast<const uint4*>(g_klo + gofs);
            uint4 a0 = gkh[0], a1 = gkh[1], a2 = gkl[0], a3 = gkl[1];
            *reinterpret_cast<uint4*>(&sKhi[trow * 72 + dof]) = a0;
            *reinterpret_cast<uint4*>(&sKhi[trow * 72 + dof + 8]) = a1;
            *reinterpret_cast<uint4*>(&sKlo[trow * 72 + dof]) = a2;
            *reinterpret_cast<uint4*>(&sKlo[trow * 72 + dof + 8]) = a3;
            const uint4* gvh = reinterpret_cast<const uint4*>(g_vhi + gofs);
            const uint4* gvl = reinterpret_cast<const uint4*>(g_vlo + gofs);
            uint4 v0 = gvh[0], v1 = gvh[1], v2 = gvl[0], v3 = gvl[1];
            __nv_bfloat16 tmph[16], tmpl[16];
            *reinterpret_cast<uint4*>(tmph) = v0;
            *reinterpret_cast<uint4*>(tmph + 8) = v1;
            *reinterpret_cast<uint4*>(tmpl) = v2;
            *reinterpret_cast<uint4*>(tmpl + 8) = v3;
#pragma unroll
            for (int j = 0; j < 16; ++j) {
                sVhi[(dof + j) * 72 + trow] = tmph[j];
                sVlo[(dof + j) * 72 + trow] = tmpl[j];
            }
        }
        __syncthreads();

        // ---- S = q k^T ----
        float s[8][4];
#pragma unroll
        for (int i = 0; i < 8; ++i)
#pragma unroll
            for (int j = 0; j < 4; ++j) s[i][j] = 0.f;
#pragma unroll
        for (int ks = 0; ks < 4; ++ks) {
            const int kk = ks * 16;
#pragma unroll
            for (int nt = 0; nt < 8; ++nt) {
                const int nn = nt * 8 + lr;
                unsigned bh0 = *reinterpret_cast<unsigned*>(&sKhi[nn * 72 + kk + 2 * lc]);
                unsigned bh1 = *reinterpret_cast<unsigned*>(&sKhi[nn * 72 + kk + 2 * lc + 8]);
                unsigned bl0 = *reinterpret_cast<unsigned*>(&sKlo[nn * 72 + kk + 2 * lc]);
                unsigned bl1 = *reinterpret_cast<unsigned*>(&sKlo[nn * 72 + kk + 2 * lc + 8]);
                mma16816(s[nt], qh[ks], bh0, bh1);
                mma16816(s[nt], qh[ks], bl0, bl1);
                mma16816(s[nt], ql[ks], bh0, bh1);
            }
        }

        // ---- biases + mask + online softmax ----
        float mx0 = -1e30f, mx1 = -1e30f;
#pragma unroll
        for (int nt = 0; nt < 8; ++nt) {
            const int col = kbase + nt * 8 + 2 * lc;
            float2 rp0 = *reinterpret_cast<const float2*>(rp_row + col);
            float2 rp1 = *reinterpret_cast<const float2*>(rp_row + 8 * S_ + col);
            float2 r20 = *reinterpret_cast<const float2*>(r2_row + col);
            float2 r21 = *reinterpret_cast<const float2*>(r2_row + 8 * S_ + col);
            int2 mk0 = *reinterpret_cast<const int2*>(mk_row + col);
            int2 mk1 = *reinterpret_cast<const int2*>(mk_row + 8 * S_ + col);
            s[nt][0] = mk0.x ? -1e30f : s[nt][0] + rp0.x + r20.x;
            s[nt][1] = mk0.y ? -1e30f : s[nt][1] + rp0.y + r20.y;
            s[nt][2] = mk1.x ? -1e30f : s[nt][2] + rp1.x + r21.x;
            s[nt][3] = mk1.y ? -1e30f : s[nt][3] + rp1.y + r21.y;
            mx0 = fmaxf(mx0, fmaxf(s[nt][0], s[nt][1]));
            mx1 = fmaxf(mx1, fmaxf(s[nt][2], s[nt][3]));
        }
        mx0 = fmaxf(mx0, __shfl_xor_sync(0xffffffffu, mx0, 1));
        mx0 = fmaxf(mx0, __shfl_xor_sync(0xffffffffu, mx0, 2));
        mx1 = fmaxf(mx1, __shfl_xor_sync(0xffffffffu, mx1, 1));
        mx1 = fmaxf(mx1, __shfl_xor_sync(0xffffffffu, mx1, 2));
        const float mn0 = fmaxf(m0, mx0), mn1 = fmaxf(m1, mx1);
        const float sc0 = ex2((m0 - mn0) * L2E), sc1 = ex2((m1 - mn1) * L2E);
        m0 = mn0; m1 = mn1;
        float rs0 = 0.f, rs1 = 0.f;
#pragma unroll
        for (int nt = 0; nt < 8; ++nt) {
            s[nt][0] = ex2((s[nt][0] - mn0) * L2E);
            s[nt][1] = ex2((s[nt][1] - mn0) * L2E);
            s[nt][2] = ex2((s[nt][2] - mn1) * L2E);
            s[nt][3] = ex2((s[nt][3] - mn1) * L2E);
            rs0 += s[nt][0] + s[nt][1];
            rs1 += s[nt][2] + s[nt][3];
        }
        rs0 += __shfl_xor_sync(0xffffffffu, rs0, 1);
        rs0 += __shfl_xor_sync(0xffffffffu, rs0, 2);
        rs1 += __shfl_xor_sync(0xffffffffu, rs1, 1);
        rs1 += __shfl_xor_sync(0xffffffffu, rs1, 2);
        l0 = l0 * sc0 + rs0;
        l1 = l1 * sc1 + rs1;
#pragma unroll
        for (int nt = 0; nt < 8; ++nt) {
            O[nt][0] *= sc0; O[nt][1] *= sc0;
            O[nt][2] *= sc1; O[nt][3] *= sc1;
        }

        // ---- O += P V  (P repacked in registers into A-frags) ----
#pragma unroll
        for (int ks = 0; ks < 4; ++ks) {
            const int kk = ks * 16;
            unsigned pah[4], pal[4];
            split2(s[2 * ks][0], s[2 * ks][1], pah[0], pal[0]);
            split2(s[2 * ks][2], s[2 * ks][3], pah[1], pal[1]);
            split2(s[2 * ks + 1][0], s[2 * ks + 1][1], pah[2], pal[2]);
            split2(s[2 * ks + 1][2], s[2 * ks + 1][3], pah[3], pal[3]);
#pragma unroll
            for (int nt = 0; nt < 8; ++nt) {
                const int nn = nt * 8 + lr;
                unsigned vh0 = *reinterpret_cast<unsigned*>(&sVhi[nn * 72 + kk + 2 * lc]);
                unsigned vh1 = *reinterpret_cast<unsigned*>(&sVhi[nn * 72 + kk + 2 * lc + 8]);
                unsigned vl0 = *reinterpret_cast<unsigned*>(&sVlo[nn * 72 + kk + 2 * lc]);
                unsigned vl1 = *reinterpret_cast<unsigned*>(&sVlo[nn * 72 + kk + 2 * lc + 8]);
                mma16816(O[nt], pah, vh0, vh1);
                mma16816(O[nt], pah, vl0, vl1);
                mma16816(O[nt], pal, vh0, vh1);
            }
        }
    }

    // ---- epilogue: normalize, write ctx [B,S,NH*HD] ----
    const float inv0 = 1.f / l0, inv1 = 1.f / l1;
    const int qrow = qbase + warp * 16 + lr;
    float* orow0 = out + ((long)b * S_ + qrow) * HID_ + h * HD_;
    float* orow1 = orow0 + 8 * HID_;
#pragma unroll
    for (int nt = 0; nt < 8; ++nt) {
        const int col = nt * 8 + 2 * lc;
        float2 w0, w1;
        w0.x = O[nt][0] * inv0; w0.y = O[nt][1] * inv0;
        w1.x = O[nt][2] * inv1; w1.y = O[nt][3] * inv1;
        *reinterpret_cast<float2*>(orow0 + col) = w0;
        *reinterpret_cast<float2*>(orow1 + col) = w1;
    }
}

// ---------------- launch ----------------
extern "C" void kernel_launch(void* const* d_in, const int* in_sizes, int n_in,
                              void* d_out, int out_size) {
    const float* hidden = (const float*)d_in[0];
    const float* rel_pos = (const float*)d_in[1];
    const float* rel2d = (const float*)d_in[2];
    const int* amask = (const int*)d_in[3];
    const float* Wq = (const float*)d_in[4];
    const float* bq = (const float*)d_in[5];
    const float* Wk = (const float*)d_in[6];
    const float* bk = (const float*)d_in[7];
    const float* Wv = (const float*)d_in[8];
    const float* bv = (const float*)d_in[9];
    float* out = (float*)d_out;

    __nv_bfloat16 *xhi, *xlo, *whi0, *wlo0, *whi1, *wlo1, *whi2, *wlo2;
    cudaGetSymbolAddress((void**)&xhi, g_Xhi);
    cudaGetSymbolAddress((void**)&xlo, g_Xlo);
    cudaGetSymbolAddress((void**)&whi0, g_Whi);
    cudaGetSymbolAddress((void**)&wlo0, g_Wlo);
    whi1 = whi0 + HID_ * HID_; whi2 = whi0 + 2 * HID_ * HID_;
    wlo1 = wlo0 + HID_ * HID_; wlo2 = wlo0 + 2 * HID_ * HID_;

    const int nx = T_ * HID_;
    const int nw = HID_ * HID_;
    split_kernel<<<(nx + 255) / 256, 256>>>(hidden, xhi, xlo, nx);
    split_kernel<<<(nw + 255) / 256, 256>>>(Wq, whi0, wlo0, nw);
    split_kernel<<<(nw + 255) / 256, 256>>>(Wk, whi1, wlo1, nw);
    split_kernel<<<(nw + 255) / 256, 256>>>(Wv, whi2, wlo2, nw);

    qkv_gemm<<<dim3(T_ / 128, HID_ / 128, 3), 256>>>(bq, bk, bv);

    attn_kernel<<<dim3(S_ / 128, NH_, B_), 256>>>(rel_pos, rel2d, amask, out);
}

// round 2
// speedup vs baseline: 1.6950x; 1.6950x over previous
#include <cuda_runtime.h>
#include <cuda_fp16.h>

#define B_   2
#define S_   2048
#define HID_ 768
#define NH_  12
#define HD_  64
#define T_   (B_*S_)   // 4096

// ---------------- scratch (static device arrays; no allocation) ----------------
__device__ __half g_X[T_*HID_];
__device__ __half g_W[3][HID_*HID_];
__device__ __half g_q[B_*NH_*S_*HD_];
__device__ __half g_k[B_*NH_*S_*HD_];
__device__ __half g_v[B_*NH_*S_*HD_];

// ---------------- helpers ----------------
__device__ __forceinline__ void mma16816(float c[4], const unsigned a[4],
                                         unsigned b0, unsigned b1) {
    asm volatile(
        "mma.sync.aligned.m16n8k16.row.col.f32.f16.f16.f32 "
        "{%0,%1,%2,%3},{%4,%5,%6,%7},{%8,%9},{%0,%1,%2,%3};\n"
        : "+f"(c[0]), "+f"(c[1]), "+f"(c[2]), "+f"(c[3])
        : "r"(a[0]), "r"(a[1]), "r"(a[2]), "r"(a[3]), "r"(b0), "r"(b1));
}

__device__ __forceinline__ float ex2(float x) {
    float y;
    asm("ex2.approx.f32 %0, %1;" : "=f"(y) : "f"(x));
    return y;
}

__device__ __forceinline__ unsigned packh2(float a, float b) {
    __half2 h = __floats2half2_rn(a, b);
    return *reinterpret_cast<unsigned*>(&h);
}

// ---------------- fp32 -> fp16 convert ----------------
__global__ void cvt_kernel(const float* __restrict__ src,
                           __half* __restrict__ dst, int n) {
    int i = (blockIdx.x * 256 + threadIdx.x) * 4;
    if (i < n) {
        float4 v = *reinterpret_cast<const float4*>(src + i);
        __half2 h0 = __floats2half2_rn(v.x, v.y);
        __half2 h1 = __floats2half2_rn(v.z, v.w);
        *reinterpret_cast<__half2*>(dst + i) = h0;
        *reinterpret_cast<__half2*>(dst + i + 2) = h1;
    }
}

// ---------------- QKV projection GEMM (fp16 single-term) ----------------
// out[t][o] = (sum_i X[t][i] * W[o][i] + bias[o]) * scale
// CTA: 128(M) x 128(N), K step 32. 8 warps as 4(M) x 2(N), warp tile 32x64.
__global__ __launch_bounds__(256) void qkv_gemm(
    const float* __restrict__ bq, const float* __restrict__ bk,
    const float* __restrict__ bv) {
    const int proj = blockIdx.z;
    const __half* __restrict__ Bw = g_W[proj];
    const float* bias = (proj == 0) ? bq : (proj == 1) ? bk : bv;
    const float scale = (proj == 0) ? 0.125f : 1.0f;
    __half* outp = (proj == 0) ? g_q : (proj == 1) ? g_k : g_v;

    const int mbase = blockIdx.x * 128, nbase = blockIdx.y * 128;
    const int tid = threadIdx.x, warp = tid >> 5, lane = tid & 31;
    const int lr = lane >> 2, lc = lane & 3;
    const int wm = (warp & 3) * 32, wn = (warp >> 2) * 64;

    __shared__ __half sA[128 * 40];
    __shared__ __half sB[128 * 40];

    float acc[2][8][4];
#pragma unroll
    for (int i = 0; i < 2; ++i)
#pragma unroll
        for (int j = 0; j < 8; ++j)
#pragma unroll
            for (int k = 0; k < 4; ++k) acc[i][j][k] = 0.f;

    const int r = tid >> 1, hf = tid & 1;  // 128 rows, 2 halves of 16 halfs

    for (int k0 = 0; k0 < HID_; k0 += 32) {
        __syncthreads();
        {
            const long ga = (long)(mbase + r) * HID_ + k0 + hf * 16;
            const uint4* pa = reinterpret_cast<const uint4*>(g_X + ga);
            uint4 a0 = pa[0], a1 = pa[1];
            *reinterpret_cast<uint4*>(&sA[r * 40 + hf * 16]) = a0;
            *reinterpret_cast<uint4*>(&sA[r * 40 + hf * 16 + 8]) = a1;
            const long gb = (long)(nbase + r) * HID_ + k0 + hf * 16;
            const uint4* pb = reinterpret_cast<const uint4*>(Bw + gb);
            uint4 b0 = pb[0], b1 = pb[1];
            *reinterpret_cast<uint4*>(&sB[r * 40 + hf * 16]) = b0;
            *reinterpret_cast<uint4*>(&sB[r * 40 + hf * 16 + 8]) = b1;
        }
        __syncthreads();
#pragma unroll
        for (int ks = 0; ks < 2; ++ks) {
            const int kk = ks * 16;
            unsigned a[2][4];
#pragma unroll
            for (int mt = 0; mt < 2; ++mt) {
                const int rr = wm + mt * 16 + lr;
                const int cc = kk + 2 * lc;
                a[mt][0] = *reinterpret_cast<unsigned*>(&sA[rr * 40 + cc]);
                a[mt][1] = *reinterpret_cast<unsigned*>(&sA[(rr + 8) * 40 + cc]);
                a[mt][2] = *reinterpret_cast<unsigned*>(&sA[rr * 40 + cc + 8]);
                a[mt][3] = *reinterpret_cast<unsigned*>(&sA[(rr + 8) * 40 + cc + 8]);
            }
#pragma unroll
            for (int nt = 0; nt < 8; ++nt) {
                const int nn = wn + nt * 8 + lr;
                const int cc = kk + 2 * lc;
                unsigned b0 = *reinterpret_cast<unsigned*>(&sB[nn * 40 + cc]);
                unsigned b1 = *reinterpret_cast<unsigned*>(&sB[nn * 40 + cc + 8]);
#pragma unroll
                for (int mt = 0; mt < 2; ++mt) {
                    mma16816(acc[mt][nt], a[mt], b0, b1);
                }
            }
        }
    }

    // write fp16 outputs in [B,NH,S,HD] layout
#pragma unroll
    for (int mt = 0; mt < 2; ++mt) {
#pragma unroll
        for (int nt = 0; nt < 8; ++nt) {
            const int row0 = mbase + wm + mt * 16 + lr;
            const int col0 = nbase + wn + nt * 8 + 2 * lc;
#pragma unroll
            for (int rr = 0; rr < 2; ++rr) {
                const int t = row0 + rr * 8;
                float v0 = (acc[mt][nt][rr * 2 + 0] + bias[col0]) * scale;
                float v1 = (acc[mt][nt][rr * 2 + 1] + bias[col0 + 1]) * scale;
                const int bb = t >> 11, ss = t & 2047;
                const int h = col0 >> 6, d = col0 & 63;
                const long oidx = (((long)bb * NH_ + h) * S_ + ss) * HD_ + d;
                *reinterpret_cast<unsigned*>(outp + oidx) = packh2(v0, v1);
            }
        }
    }
}

// ---------------- flash attention (fp16 single-term) ----------------
// CTA: 128 q rows (8 warps x 16), key blocks of 64, online softmax.
__global__ __launch_bounds__(256, 2) void attn_kernel(
    const float* __restrict__ rel_pos, const float* __restrict__ rel2d,
    const int* __restrict__ amask, float* __restrict__ out) {
    const int qt = blockIdx.x, h = blockIdx.y, b = blockIdx.z;
    const int bh = b * NH_ + h;
    const int tid = threadIdx.x, warp = tid >> 5, lane = tid & 31;
    const int qbase = qt * 128;
    const int lr = lane >> 2, lc = lane & 3;
    const float L2E = 1.4426950408889634f;

    __shared__ __half sK[64 * 72];
    __shared__ __half sVT[64 * 72];  // transposed: [d][t]

    // q fragments (A-frags), loaded once directly from global
    unsigned qf[4][4];
    {
        const __half* qp = g_q + ((long)bh * S_ + qbase + warp * 16) * HD_;
#pragma unroll
        for (int ks = 0; ks < 4; ++ks) {
            const int b0 = lr * HD_ + ks * 16 + 2 * lc;
            qf[ks][0] = *reinterpret_cast<const unsigned*>(qp + b0);
            qf[ks][1] = *reinterpret_cast<const unsigned*>(qp + b0 + 8 * HD_);
            qf[ks][2] = *reinterpret_cast<const unsigned*>(qp + b0 + 8);
            qf[ks][3] = *reinterpret_cast<const unsigned*>(qp + b0 + 8 * HD_ + 8);
        }
    }

    float O[8][4];
#pragma unroll
    for (int i = 0; i < 8; ++i)
#pragma unroll
        for (int j = 0; j < 4; ++j) O[i][j] = 0.f;
    float m0 = -1e30f, m1 = -1e30f, l0 = 0.f, l1 = 0.f;

    const float* rp_row = rel_pos + ((long)bh * S_ + qbase + warp * 16 + lr) * S_;
    const float* r2_row = rel2d + ((long)bh * S_ + qbase + warp * 16 + lr) * S_;
    const int* mk_row = amask + ((long)b * S_ + qbase + warp * 16 + lr) * S_;

    const int trow = tid >> 2;         // 0..63
    const int dof = (tid & 3) * 16;    // 0,16,32,48

    for (int kb = 0; kb < 32; ++kb) {
        const int kbase = kb * 64;
        __syncthreads();
        {
            const long gofs = ((long)bh * S_ + kbase + trow) * HD_ + dof;
            const uint4* gk = reinterpret_cast<const uint4*>(g_k + gofs);
            uint4 a0 = gk[0], a1 = gk[1];
            *reinterpret_cast<uint4*>(&sK[trow * 72 + dof]) = a0;
            *reinterpret_cast<uint4*>(&sK[trow * 72 + dof + 8]) = a1;
            const uint4* gv = reinterpret_cast<const uint4*>(g_v + gofs);
            uint4 v0 = gv[0], v1 = gv[1];
            __half tmp[16];
            *reinterpret_cast<uint4*>(tmp) = v0;
            *reinterpret_cast<uint4*>(tmp + 8) = v1;
#pragma unroll
            for (int j = 0; j < 16; ++j) {
                sVT[(dof + j) * 72 + trow] = tmp[j];
            }
        }
        __syncthreads();

        // ---- S = q k^T ----
        float s[8][4];
#pragma unroll
        for (int i = 0; i < 8; ++i)
#pragma unroll
            for (int j = 0; j < 4; ++j) s[i][j] = 0.f;
#pragma unroll
        for (int ks = 0; ks < 4; ++ks) {
            const int kk = ks * 16;
#pragma unroll
            for (int nt = 0; nt < 8; ++nt) {
                const int nn = nt * 8 + lr;
                unsigned b0 = *reinterpret_cast<unsigned*>(&sK[nn * 72 + kk + 2 * lc]);
                unsigned b1 = *reinterpret_cast<unsigned*>(&sK[nn * 72 + kk + 2 * lc + 8]);
                mma16816(s[nt], qf[ks], b0, b1);
            }
        }

        // ---- biases + mask + online softmax ----
        float mx0 = -1e30f, mx1 = -1e30f;
#pragma unroll
        for (int nt = 0; nt < 8; ++nt) {
            const int col = kbase + nt * 8 + 2 * lc;
            float2 rp0 = *reinterpret_cast<const float2*>(rp_row + col);
            float2 rp1 = *reinterpret_cast<const float2*>(rp_row + 8 * S_ + col);
            float2 r20 = *reinterpret_cast<const float2*>(r2_row + col);
            float2 r21 = *reinterpret_cast<const float2*>(r2_row + 8 * S_ + col);
            int2 mk0 = *reinterpret_cast<const int2*>(mk_row + col);
            int2 mk1 = *reinterpret_cast<const int2*>(mk_row + 8 * S_ + col);
            s[nt][0] = mk0.x ? -1e30f : s[nt][0] + rp0.x + r20.x;
            s[nt][1] = mk0.y ? -1e30f : s[nt][1] + rp0.y + r20.y;
            s[nt][2] = mk1.x ? -1e30f : s[nt][2] + rp1.x + r21.x;
            s[nt][3] = mk1.y ? -1e30f : s[nt][3] + rp1.y + r21.y;
            mx0 = fmaxf(mx0, fmaxf(s[nt][0], s[nt][1]));
            mx1 = fmaxf(mx1, fmaxf(s[nt][2], s[nt][3]));
        }
        mx0 = fmaxf(mx0, __shfl_xor_sync(0xffffffffu, mx0, 1));
        mx0 = fmaxf(mx0, __shfl_xor_sync(0xffffffffu, mx0, 2));
        mx1 = fmaxf(mx1, __shfl_xor_sync(0xffffffffu, mx1, 1));
        mx1 = fmaxf(mx1, __shfl_xor_sync(0xffffffffu, mx1, 2));
        const float mn0 = fmaxf(m0, mx0), mn1 = fmaxf(m1, mx1);
        const float sc0 = ex2((m0 - mn0) * L2E), sc1 = ex2((m1 - mn1) * L2E);
        m0 = mn0; m1 = mn1;
        float rs0 = 0.f, rs1 = 0.f;
#pragma unroll
        for (int nt = 0; nt < 8; ++nt) {
            s[nt][0] = ex2((s[nt][0] - mn0) * L2E);
            s[nt][1] = ex2((s[nt][1] - mn0) * L2E);
            s[nt][2] = ex2((s[nt][2] - mn1) * L2E);
            s[nt][3] = ex2((s[nt][3] - mn1) * L2E);
            rs0 += s[nt][0] + s[nt][1];
            rs1 += s[nt][2] + s[nt][3];
        }
        rs0 += __shfl_xor_sync(0xffffffffu, rs0, 1);
        rs0 += __shfl_xor_sync(0xffffffffu, rs0, 2);
        rs1 += __shfl_xor_sync(0xffffffffu, rs1, 1);
        rs1 += __shfl_xor_sync(0xffffffffu, rs1, 2);
        l0 = l0 * sc0 + rs0;
        l1 = l1 * sc1 + rs1;
#pragma unroll
        for (int nt = 0; nt < 8; ++nt) {
            O[nt][0] *= sc0; O[nt][1] *= sc0;
            O[nt][2] *= sc1; O[nt][3] *= sc1;
        }

        // ---- O += P V  (P packed in registers into A-frags) ----
#pragma unroll
        for (int ks = 0; ks < 4; ++ks) {
            const int kk = ks * 16;
            unsigned pa[4];
            pa[0] = packh2(s[2 * ks][0], s[2 * ks][1]);
            pa[1] = packh2(s[2 * ks][2], s[2 * ks][3]);
            pa[2] = packh2(s[2 * ks + 1][0], s[2 * ks + 1][1]);
            pa[3] = packh2(s[2 * ks + 1][2], s[2 * ks + 1][3]);
#pragma unroll
            for (int nt = 0; nt < 8; ++nt) {
                const int nn = nt * 8 + lr;
                unsigned v0 = *reinterpret_cast<unsigned*>(&sVT[nn * 72 + kk + 2 * lc]);
                unsigned v1 = *reinterpret_cast<unsigned*>(&sVT[nn * 72 + kk + 2 * lc + 8]);
                mma16816(O[nt], pa, v0, v1);
            }
        }
    }

    // ---- epilogue: normalize, write ctx [B,S,NH*HD] ----
    const float inv0 = 1.f / l0, inv1 = 1.f / l1;
    const int qrow = qbase + warp * 16 + lr;
    float* orow0 = out + ((long)b * S_ + qrow) * HID_ + h * HD_;
    float* orow1 = orow0 + 8 * HID_;
#pragma unroll
    for (int nt = 0; nt < 8; ++nt) {
        const int col = nt * 8 + 2 * lc;
        float2 w0, w1;
        w0.x = O[nt][0] * inv0; w0.y = O[nt][1] * inv0;
        w1.x = O[nt][2] * inv1; w1.y = O[nt][3] * inv1;
        *reinterpret_cast<float2*>(orow0 + col) = w0;
        *reinterpret_cast<float2*>(orow1 + col) = w1;
    }
}

// ---------------- launch ----------------
extern "C" void kernel_launch(void* const* d_in, const int* in_sizes, int n_in,
                              void* d_out, int out_size) {
    const float* hidden = (const float*)d_in[0];
    const float* rel_pos = (const float*)d_in[1];
    const float* rel2d = (const float*)d_in[2];
    const int* amask = (const int*)d_in[3];
    const float* Wq = (const float*)d_in[4];
    const float* bq = (const float*)d_in[5];
    const float* Wk = (const float*)d_in[6];
    const float* bk = (const float*)d_in[7];
    const float* Wv = (const float*)d_in[8];
    const float* bv = (const float*)d_in[9];
    float* out = (float*)d_out;

    __half *xp, *wp;
    cudaGetSymbolAddress((void**)&xp, g_X);
    cudaGetSymbolAddress((void**)&wp, g_W);

    const int nx = T_ * HID_;
    const int nw = HID_ * HID_;
    cvt_kernel<<<(nx / 4 + 255) / 256, 256>>>(hidden, xp, nx);
    cvt_kernel<<<(nw / 4 + 255) / 256, 256>>>(Wq, wp, nw);
    cvt_kernel<<<(nw / 4 + 255) / 256, 256>>>(Wk, wp + nw, nw);
    cvt_kernel<<<(nw / 4 + 255) / 256, 256>>>(Wv, wp + 2 * nw, nw);

    qkv_gemm<<<dim3(T_ / 128, HID_ / 128, 3), 256>>>(bq, bk, bv);

    attn_kernel<<<dim3(S_ / 128, NH_, B_), 256>>>(rel_pos, rel2d, amask, out);
}

// round 3
// speedup vs baseline: 1.9863x; 1.1719x over previous
#include <cuda_runtime.h>
#include <cuda_fp16.h>

#define B_   2
#define S_   2048
#define HID_ 768
#define NH_  12
#define HD_  64
#define T_   (B_*S_)   // 4096

// ---------------- scratch (static device arrays; no allocation) ----------------
__device__ __half g_X[T_*HID_];
__device__ __half g_W[3][HID_*HID_];
__device__ __half g_q[B_*NH_*S_*HD_];
__device__ __half g_k[B_*NH_*S_*HD_];
__device__ __half g_v[B_*NH_*S_*HD_];

// ---------------- helpers ----------------
__device__ __forceinline__ void mma16816(float c[4], const unsigned a[4],
                                         unsigned b0, unsigned b1) {
    asm volatile(
        "mma.sync.aligned.m16n8k16.row.col.f32.f16.f16.f32 "
        "{%0,%1,%2,%3},{%4,%5,%6,%7},{%8,%9},{%0,%1,%2,%3};\n"
        : "+f"(c[0]), "+f"(c[1]), "+f"(c[2]), "+f"(c[3])
        : "r"(a[0]), "r"(a[1]), "r"(a[2]), "r"(a[3]), "r"(b0), "r"(b1));
}

__device__ __forceinline__ float ex2(float x) {
    float y;
    asm("ex2.approx.f32 %0, %1;" : "=f"(y) : "f"(x));
    return y;
}

__device__ __forceinline__ unsigned packh2(float a, float b) {
    __half2 h = __floats2half2_rn(a, b);
    return *reinterpret_cast<unsigned*>(&h);
}

__device__ __forceinline__ void cp16(unsigned dst, const void* src) {
    asm volatile("cp.async.cg.shared.global [%0], [%1], 16;\n" ::
                 "r"(dst), "l"(src));
}
__device__ __forceinline__ void cp_commit() {
    asm volatile("cp.async.commit_group;\n" ::: "memory");
}
__device__ __forceinline__ void cp_wait1() {
    asm volatile("cp.async.wait_group 1;\n" ::: "memory");
}
__device__ __forceinline__ void cp_wait0() {
    asm volatile("cp.async.wait_group 0;\n" ::: "memory");
}

__device__ __forceinline__ void ldmx4(unsigned &r0, unsigned &r1, unsigned &r2,
                                      unsigned &r3, unsigned addr) {
    asm volatile(
        "ldmatrix.sync.aligned.m8n8.x4.shared.b16 {%0,%1,%2,%3}, [%4];\n"
        : "=r"(r0), "=r"(r1), "=r"(r2), "=r"(r3) : "r"(addr));
}
__device__ __forceinline__ void ldmx4t(unsigned &r0, unsigned &r1, unsigned &r2,
                                       unsigned &r3, unsigned addr) {
    asm volatile(
        "ldmatrix.sync.aligned.m8n8.x4.trans.shared.b16 {%0,%1,%2,%3}, [%4];\n"
        : "=r"(r0), "=r"(r1), "=r"(r2), "=r"(r3) : "r"(addr));
}

// ---------------- fp32 -> fp16 convert ----------------
__global__ void cvt_kernel(const float* __restrict__ src,
                           __half* __restrict__ dst, int n) {
    int i = (blockIdx.x * 256 + threadIdx.x) * 4;
    if (i < n) {
        float4 v = *reinterpret_cast<const float4*>(src + i);
        __half2 h0 = __floats2half2_rn(v.x, v.y);
        __half2 h1 = __floats2half2_rn(v.z, v.w);
        *reinterpret_cast<__half2*>(dst + i) = h0;
        *reinterpret_cast<__half2*>(dst + i + 2) = h1;
    }
}

// ---------------- QKV projection GEMM (fp16, cp.async 2-stage) ----------------
// CTA: 128(M) x 128(N), K step 32. 8 warps as 4(M) x 2(N), warp tile 32x64.
__global__ __launch_bounds__(256) void qkv_gemm(
    const float* __restrict__ bq, const float* __restrict__ bk,
    const float* __restrict__ bv) {
    const int proj = blockIdx.z;
    const __half* __restrict__ Bw = g_W[proj];
    const float* bias = (proj == 0) ? bq : (proj == 1) ? bk : bv;
    const float scale = (proj == 0) ? 0.125f : 1.0f;
    __half* outp = (proj == 0) ? g_q : (proj == 1) ? g_k : g_v;

    const int mbase = blockIdx.x * 128, nbase = blockIdx.y * 128;
    const int tid = threadIdx.x, warp = tid >> 5, lane = tid & 31;
    const int lr = lane >> 2, lc = lane & 3;
    const int wm = (warp & 3) * 32, wn = (warp >> 2) * 64;

    __shared__ __half sA[2][128 * 40];
    __shared__ __half sB[2][128 * 40];

    const unsigned sAu = (unsigned)__cvta_generic_to_shared(&sA[0][0]);
    const unsigned sBu = (unsigned)__cvta_generic_to_shared(&sB[0][0]);

    const int g = lane >> 3, rw = lane & 7;
    // ldmatrix byte offsets (pitch 40 halfs = 80B)
    const unsigned offA = (unsigned)(((g & 1) * 8 + rw) * 80 + (g >> 1) * 16);
    const unsigned offB = (unsigned)(((g >> 1) * 8 + rw) * 80 + (g & 1) * 16);

    float acc[2][8][4];
#pragma unroll
    for (int i = 0; i < 2; ++i)
#pragma unroll
        for (int j = 0; j < 8; ++j)
#pragma unroll
            for (int k = 0; k < 4; ++k) acc[i][j][k] = 0.f;

    auto issue = [&](int it) {
        const int cur = it & 1;
        const int k0 = it * 32;
#pragma unroll
        for (int i = 0; i < 4; ++i) {
            const int c = tid + 256 * i;
            if (c < 512) {
                const int row = c >> 2, cc = c & 3;
                cp16(sAu + (unsigned)(cur * 128 * 80 + row * 80 + cc * 16),
                     g_X + (long)(mbase + row) * HID_ + k0 + cc * 8);
            } else {
                const int row = (c - 512) >> 2, cc = c & 3;
                cp16(sBu + (unsigned)(cur * 128 * 80 + row * 80 + cc * 16),
                     Bw + (long)(nbase + row) * HID_ + k0 + cc * 8);
            }
        }
        cp_commit();
    };

    issue(0);
    const int NIT = HID_ / 32;  // 24
    for (int it = 0; it < NIT; ++it) {
        const int cur = it & 1;
        if (it > 0) __syncthreads();
        if (it + 1 < NIT) { issue(it + 1); cp_wait1(); }
        else cp_wait0();
        __syncthreads();

        const unsigned sAc = sAu + cur * 128 * 80;
        const unsigned sBc = sBu + cur * 128 * 80;
#pragma unroll
        for (int ks = 0; ks < 2; ++ks) {
            const int kkB = ks * 32;  // bytes (16 halfs)
            unsigned a[2][4];
#pragma unroll
            for (int mt = 0; mt < 2; ++mt) {
                ldmx4(a[mt][0], a[mt][1], a[mt][2], a[mt][3],
                      sAc + offA + (wm + mt * 16) * 80 + kkB);
            }
#pragma unroll
            for (int np = 0; np < 4; ++np) {
                unsigned b0, b1, b2, b3;
                ldmx4(b0, b1, b2, b3,
                      sBc + offB + (wn + np * 16) * 80 + kkB);
#pragma unroll
                for (int mt = 0; mt < 2; ++mt) {
                    mma16816(acc[mt][2 * np], a[mt], b0, b1);
                    mma16816(acc[mt][2 * np + 1], a[mt], b2, b3);
                }
            }
        }
    }

    // write fp16 outputs in [B,NH,S,HD] layout
#pragma unroll
    for (int mt = 0; mt < 2; ++mt) {
#pragma unroll
        for (int nt = 0; nt < 8; ++nt) {
            const int row0 = mbase + wm + mt * 16 + lr;
            const int col0 = nbase + wn + nt * 8 + 2 * lc;
#pragma unroll
            for (int rr = 0; rr < 2; ++rr) {
                const int t = row0 + rr * 8;
                float v0 = (acc[mt][nt][rr * 2 + 0] + bias[col0]) * scale;
                float v1 = (acc[mt][nt][rr * 2 + 1] + bias[col0 + 1]) * scale;
                const int bb = t >> 11, ss = t & 2047;
                const int hh = col0 >> 6, d = col0 & 63;
                const long oidx = (((long)bb * NH_ + hh) * S_ + ss) * HD_ + d;
                *reinterpret_cast<unsigned*>(outp + oidx) = packh2(v0, v1);
            }
        }
    }
}

// ---------------- flash attention (cp.async pipelined, ldmatrix) ----------------
// CTA: 128 q rows (8 warps x 16), key blocks of 32, online softmax.
#define KB_   32
#define NITER (S_ / KB_)   // 64
// stage byte offsets (all rows use 144B pitch)
#define OFF_K  0
#define OFF_V  4608
#define OFF_R  9216
#define OFF_R2 27648
#define OFF_M  46080
#define STAGE_ 64512

__global__ __launch_bounds__(256) void attn_kernel(
    const float* __restrict__ rel_pos, const float* __restrict__ rel2d,
    const int* __restrict__ amask, float* __restrict__ out) {
    extern __shared__ char smem[];
    const int qt = blockIdx.x, h = blockIdx.y, b = blockIdx.z;
    const int bh = b * NH_ + h;
    const int tid = threadIdx.x, warp = tid >> 5, lane = tid & 31;
    const int qbase = qt * 128;
    const int lr = lane >> 2, lc = lane & 3;
    const float L2E = 1.4426950408889634f;

    const unsigned sbase = (unsigned)__cvta_generic_to_shared(smem);
    const int g = lane >> 3, rw = lane & 7;
    // K: row = nn + (g>>1)*8 + rw, col = kk + (g&1)*8   (pitch 72 halfs = 144B)
    const unsigned offK = (unsigned)(((g >> 1) * 8 + rw) * 144 + (g & 1) * 16);
    // V(trans): row = kk + (g&1)*8 + rw, col = nn + (g>>1)*8
    const unsigned offV = (unsigned)(((g & 1) * 8 + rw) * 144 + (g >> 1) * 16);

    // q fragments (A-frags), loaded once directly from global
    unsigned qf[4][4];
    {
        const __half* qp = g_q + ((long)bh * S_ + qbase + warp * 16) * HD_;
#pragma unroll
        for (int ks = 0; ks < 4; ++ks) {
            const int b0 = lr * HD_ + ks * 16 + 2 * lc;
            qf[ks][0] = *reinterpret_cast<const unsigned*>(qp + b0);
            qf[ks][1] = *reinterpret_cast<const unsigned*>(qp + b0 + 8 * HD_);
            qf[ks][2] = *reinterpret_cast<const unsigned*>(qp + b0 + 8);
            qf[ks][3] = *reinterpret_cast<const unsigned*>(qp + b0 + 8 * HD_ + 8);
        }
    }

    auto issue = [&](int kb) {
        const int cur = kb & 1;
        const unsigned sb = sbase + cur * STAGE_;
        const int kbase = kb * KB_;
        {
            const int row = tid >> 3, cc = tid & 7;
            const long go = ((long)bh * S_ + kbase + row) * HD_ + cc * 8;
            cp16(sb + OFF_K + row * 144 + cc * 16, g_k + go);
            cp16(sb + OFF_V + row * 144 + cc * 16, g_v + go);
        }
#pragma unroll
        for (int i = 0; i < 4; ++i) {
            const int c = tid + 256 * i;
            const int row = c >> 3, cc = c & 7;
            const long ro = ((long)bh * S_ + qbase + row) * S_ + kbase + cc * 4;
            cp16(sb + OFF_R + row * 144 + cc * 16, rel_pos + ro);
            cp16(sb + OFF_R2 + row * 144 + cc * 16, rel2d + ro);
            const long mo = ((long)b * S_ + qbase + row) * S_ + kbase + cc * 4;
            cp16(sb + OFF_M + row * 144 + cc * 16, amask + mo);
        }
        cp_commit();
    };

    float O[8][4];
#pragma unroll
    for (int i = 0; i < 8; ++i)
#pragma unroll
        for (int j = 0; j < 4; ++j) O[i][j] = 0.f;
    float m0 = -1e30f, m1 = -1e30f, l0 = 0.f, l1 = 0.f;

    issue(0);

    for (int kb = 0; kb < NITER; ++kb) {
        const int cur = kb & 1;
        if (kb > 0) __syncthreads();
        if (kb + 1 < NITER) { issue(kb + 1); cp_wait1(); }
        else cp_wait0();
        __syncthreads();

        const unsigned sKa = sbase + cur * STAGE_ + OFF_K;
        const unsigned sVa = sbase + cur * STAGE_ + OFF_V;
        const float* sR = (const float*)(smem + cur * STAGE_ + OFF_R);
        const float* sR2 = (const float*)(smem + cur * STAGE_ + OFF_R2);
        const int* sM = (const int*)(smem + cur * STAGE_ + OFF_M);

        // ---- S = q k^T ----
        float s[4][4];
#pragma unroll
        for (int i = 0; i < 4; ++i)
#pragma unroll
            for (int j = 0; j < 4; ++j) s[i][j] = 0.f;
#pragma unroll
        for (int ks = 0; ks < 4; ++ks) {
#pragma unroll
            for (int np = 0; np < 2; ++np) {
                unsigned b0, b1, b2, b3;
                ldmx4(b0, b1, b2, b3, sKa + offK + np * 16 * 144 + ks * 32);
                mma16816(s[2 * np], qf[ks], b0, b1);
                mma16816(s[2 * np + 1], qf[ks], b2, b3);
            }
        }

        // ---- biases + mask (from smem) + online softmax ----
        const int rbase = (warp * 16 + lr) * 36;
        float mx0 = -1e30f, mx1 = -1e30f;
#pragma unroll
        for (int nt = 0; nt < 4; ++nt) {
            const int col = nt * 8 + 2 * lc;
            float2 rp0 = *reinterpret_cast<const float2*>(sR + rbase + col);
            float2 rp1 = *reinterpret_cast<const float2*>(sR + rbase + 8 * 36 + col);
            float2 r20 = *reinterpret_cast<const float2*>(sR2 + rbase + col);
            float2 r21 = *reinterpret_cast<const float2*>(sR2 + rbase + 8 * 36 + col);
            int2 mk0 = *reinterpret_cast<const int2*>(sM + rbase + col);
            int2 mk1 = *reinterpret_cast<const int2*>(sM + rbase + 8 * 36 + col);
            s[nt][0] = mk0.x ? -1e30f : s[nt][0] + rp0.x + r20.x;
            s[nt][1] = mk0.y ? -1e30f : s[nt][1] + rp0.y + r20.y;
            s[nt][2] = mk1.x ? -1e30f : s[nt][2] + rp1.x + r21.x;
            s[nt][3] = mk1.y ? -1e30f : s[nt][3] + rp1.y + r21.y;
            mx0 = fmaxf(mx0, fmaxf(s[nt][0], s[nt][1]));
            mx1 = fmaxf(mx1, fmaxf(s[nt][2], s[nt][3]));
        }
        mx0 = fmaxf(mx0, __shfl_xor_sync(0xffffffffu, mx0, 1));
        mx0 = fmaxf(mx0, __shfl_xor_sync(0xffffffffu, mx0, 2));
        mx1 = fmaxf(mx1, __shfl_xor_sync(0xffffffffu, mx1, 1));
        mx1 = fmaxf(mx1, __shfl_xor_sync(0xffffffffu, mx1, 2));
        const float mn0 = fmaxf(m0, mx0), mn1 = fmaxf(m1, mx1);
        const float mnL0 = mn0 * L2E, mnL1 = mn1 * L2E;
        const float sc0 = ex2(m0 * L2E - mnL0), sc1 = ex2(m1 * L2E - mnL1);
        m0 = mn0; m1 = mn1;
        float rs0 = 0.f, rs1 = 0.f;
#pragma unroll
        for (int nt = 0; nt < 4; ++nt) {
            s[nt][0] = ex2(fmaf(s[nt][0], L2E, -mnL0));
            s[nt][1] = ex2(fmaf(s[nt][1], L2E, -mnL0));
            s[nt][2] = ex2(fmaf(s[nt][2], L2E, -mnL1));
            s[nt][3] = ex2(fmaf(s[nt][3], L2E, -mnL1));
            rs0 += s[nt][0] + s[nt][1];
            rs1 += s[nt][2] + s[nt][3];
        }
        rs0 += __shfl_xor_sync(0xffffffffu, rs0, 1);
        rs0 += __shfl_xor_sync(0xffffffffu, rs0, 2);
        rs1 += __shfl_xor_sync(0xffffffffu, rs1, 1);
        rs1 += __shfl_xor_sync(0xffffffffu, rs1, 2);
        l0 = l0 * sc0 + rs0;
        l1 = l1 * sc1 + rs1;
#pragma unroll
        for (int nt = 0; nt < 8; ++nt) {
            O[nt][0] *= sc0; O[nt][1] *= sc0;
            O[nt][2] *= sc1; O[nt][3] *= sc1;
        }

        // ---- O += P V  (V b-frags via ldmatrix.trans, no smem transpose) ----
#pragma unroll
        for (int ks2 = 0; ks2 < 2; ++ks2) {
            unsigned pa[4];
            pa[0] = packh2(s[2 * ks2][0], s[2 * ks2][1]);
            pa[1] = packh2(s[2 * ks2][2], s[2 * ks2][3]);
            pa[2] = packh2(s[2 * ks2 + 1][0], s[2 * ks2 + 1][1]);
            pa[3] = packh2(s[2 * ks2 + 1][2], s[2 * ks2 + 1][3]);
#pragma unroll
            for (int nb = 0; nb < 4; ++nb) {
                unsigned v0, v1, v2, v3;
                ldmx4t(v0, v1, v2, v3,
                       sVa + offV + ks2 * 16 * 144 + nb * 32);
                mma16816(O[2 * nb], pa, v0, v1);
                mma16816(O[2 * nb + 1], pa, v2, v3);
            }
        }
    }

    // ---- epilogue: normalize, write ctx [B,S,NH*HD] ----
    const float inv0 = 1.f / l0, inv1 = 1.f / l1;
    const int qrow = qbase + warp * 16 + lr;
    float* orow0 = out + ((long)b * S_ + qrow) * HID_ + h * HD_;
    float* orow1 = orow0 + 8 * HID_;
#pragma unroll
    for (int nt = 0; nt < 8; ++nt) {
        const int col = nt * 8 + 2 * lc;
        float2 w0, w1;
        w0.x = O[nt][0] * inv0; w0.y = O[nt][1] * inv0;
        w1.x = O[nt][2] * inv1; w1.y = O[nt][3] * inv1;
        *reinterpret_cast<float2*>(orow0 + col) = w0;
        *reinterpret_cast<float2*>(orow1 + col) = w1;
    }
}

// ---------------- launch ----------------
extern "C" void kernel_launch(void* const* d_in, const int* in_sizes, int n_in,
                              void* d_out, int out_size) {
    const float* hidden = (const float*)d_in[0];
    const float* rel_pos = (const float*)d_in[1];
    const float* rel2d = (const float*)d_in[2];
    const int* amask = (const int*)d_in[3];
    const float* Wq = (const float*)d_in[4];
    const float* bq = (const float*)d_in[5];
    const float* Wk = (const float*)d_in[6];
    const float* bk = (const float*)d_in[7];
    const float* Wv = (const float*)d_in[8];
    const float* bv = (const float*)d_in[9];
    float* out = (float*)d_out;

    __half *xp, *wp;
    cudaGetSymbolAddress((void**)&xp, g_X);
    cudaGetSymbolAddress((void**)&wp, g_W);

    const int nx = T_ * HID_;
    const int nw = HID_ * HID_;
    cvt_kernel<<<(nx / 4 + 255) / 256, 256>>>(hidden, xp, nx);
    cvt_kernel<<<(nw / 4 + 255) / 256, 256>>>(Wq, wp, nw);
    cvt_kernel<<<(nw / 4 + 255) / 256, 256>>>(Wk, wp + nw, nw);
    cvt_kernel<<<(nw / 4 + 255) / 256, 256>>>(Wv, wp + 2 * nw, nw);

    qkv_gemm<<<dim3(T_ / 128, HID_ / 128, 3), 256>>>(bq, bk, bv);

    cudaFuncSetAttribute(attn_kernel,
                         cudaFuncAttributeMaxDynamicSharedMemorySize,
                         2 * STAGE_);
    attn_kernel<<<dim3(S_ / 128, NH_, B_), 256, 2 * STAGE_>>>(
        rel_pos, rel2d, amask, out);
}